// round 15
// baseline (speedup 1.0000x reference)
#include <cuda_runtime.h>
#include <cuda_fp16.h>
#include <cstdint>

#define Nn 4
#define Cc 128
#define Hh 256
#define Ww 256
#define HW (Hh*Ww)

// ---------------- scratch (device globals; allocation-free) ----------------
__device__ float g_dk[(size_t)Nn*9*HW];                        // dyn kernels
__device__ float g_fused[(size_t)Nn*Cc*HW];                    // refine out NCHW
__device__ __align__(256) __half g_cat[(size_t)Nn*HW*256];     // cat NHWC fp16
__device__ __align__(256) __half g_p  [(size_t)Nn*HW*Cc];      // p NHWC fp16
__device__ __align__(256) __half g_w  [18*128*64];             // joint W fp16
__device__ __align__(256) __half g_rw [4*128*64];              // refine W fp16

// ---------------------------------------------------------------------------
__device__ __forceinline__ void mma16816(float* d, const uint32_t* a,
                                         uint32_t b0, uint32_t b1) {
    asm volatile(
        "mma.sync.aligned.m16n8k16.row.col.f32.f16.f16.f32 "
        "{%0,%1,%2,%3}, {%4,%5,%6,%7}, {%8,%9}, {%0,%1,%2,%3};"
        : "+f"(d[0]), "+f"(d[1]), "+f"(d[2]), "+f"(d[3])
        : "r"(a[0]), "r"(a[1]), "r"(a[2]), "r"(a[3]), "r"(b0), "r"(b1));
}
__device__ __forceinline__ void ldmat_x4(uint32_t* r, uint32_t saddr) {
    asm volatile("ldmatrix.sync.aligned.m8n8.x4.shared.b16 {%0,%1,%2,%3}, [%4];"
        : "=r"(r[0]), "=r"(r[1]), "=r"(r[2]), "=r"(r[3]) : "r"(saddr));
}
__device__ __forceinline__ uint32_t pack_h2(__half a, __half b) {
    __half2 h2; h2.x = a; h2.y = b;
    return *(uint32_t*)&h2;
}

// ---------------------------------------------------------------------------
// K1: dyn_kernel conv(ms, dyn_w[9,128,3,3]) + b, L1-normalized over 9 taps.
// ---------------------------------------------------------------------------
__global__ __launch_bounds__(128) void k1_dynkernel(
    const float* __restrict__ ms,
    const float* __restrict__ dyn_w,
    const float* __restrict__ dyn_b)
{
    const int w0 = blockIdx.x * 128;
    const int h  = blockIdx.y;
    const int n  = blockIdx.z;
    const int tid = threadIdx.x;

    __shared__ float Xs[3][130];
    __shared__ __align__(16) float Wt[9][12];   // [tap][k], 48B rows

    float acc[9];
#pragma unroll
    for (int k = 0; k < 9; k++) acc[k] = dyn_b[k];

    for (int ic = 0; ic < Cc; ic++) {
        const float* mp = ms + ((size_t)(n*Cc + ic))*HW;
        for (int idx = tid; idx < 3*130; idx += 128) {
            int r = idx / 130, cc2 = idx % 130;
            int hh = h + r - 1, ww = w0 + cc2 - 1;
            float v = 0.f;
            if (hh >= 0 && hh < Hh && ww >= 0 && ww < Ww) v = mp[hh*Ww + ww];
            Xs[r][cc2] = v;
        }
        if (tid < 81)
            Wt[tid%9][tid/9] = dyn_w[(tid/9)*(Cc*9) + ic*9 + (tid%9)];
        __syncthreads();

#pragma unroll
        for (int tap = 0; tap < 9; tap++) {
            float xv = Xs[tap/3][tid + (tap%3)];
            float4 wa = *(const float4*)&Wt[tap][0];
            float4 wb = *(const float4*)&Wt[tap][4];
            float w8  = Wt[tap][8];
            acc[0] += wa.x*xv; acc[1] += wa.y*xv; acc[2] += wa.z*xv; acc[3] += wa.w*xv;
            acc[4] += wb.x*xv; acc[5] += wb.y*xv; acc[6] += wb.z*xv; acc[7] += wb.w*xv;
            acc[8] += w8*xv;
        }
        __syncthreads();
    }

    float denom = 0.f;
#pragma unroll
    for (int k = 0; k < 9; k++) denom += fabsf(acc[k]);
    float inv = 1.f / denom;
#pragma unroll
    for (int k = 0; k < 9; k++)
        g_dk[((size_t)(n*9 + k))*HW + (size_t)h*Ww + w0 + tid] = acc[k] * inv;
}

// ---------------------------------------------------------------------------
// K2: concat tensor in NHWC fp16. Warp-private tiles, register-prefetched
// halo loads.
// ---------------------------------------------------------------------------
__global__ __launch_bounds__(256) void k2_cat_nhwc(
    const float* __restrict__ ms,
    const float* __restrict__ fix_w,
    const float* __restrict__ bn1_g, const float* __restrict__ bn1_b,
    const float* __restrict__ bn1_m, const float* __restrict__ bn1_v,
    const float* __restrict__ bn2_g, const float* __restrict__ bn2_b,
    const float* __restrict__ bn2_m, const float* __restrict__ bn2_v)
{
    const int w0 = blockIdx.x * 32;
    const int h  = blockIdx.y;
    const int n  = blockIdx.z;
    const int tid = threadIdx.x;
    const int lane = tid & 31;

    __shared__ float dks[9][32];
    __shared__ float Xs[8][3][34];
    __shared__ float s1a[128], t1a[128], s2a[128], t2a[128];
    __shared__ float fws[128][10];
    __shared__ __half s_cat[32][264];

    if (tid < 128) {
        float s1 = bn1_g[tid] * rsqrtf(bn1_v[tid] + 1e-5f);
        s1a[tid] = s1; t1a[tid] = bn1_b[tid] - bn1_m[tid]*s1;
        float s2 = bn2_g[tid] * rsqrtf(bn2_v[tid] + 1e-5f);
        s2a[tid] = s2; t2a[tid] = bn2_b[tid] - bn2_m[tid]*s2;
    }
    for (int idx = tid; idx < 1152; idx += 256)
        fws[idx/9][idx%9] = fix_w[idx];
    for (int idx = tid; idx < 288; idx += 256) {
        int tap = idx >> 5, px = idx & 31;
        dks[tap][px] = g_dk[((size_t)(n*9 + tap))*HW + (size_t)h*Ww + w0 + px];
    }
    __syncthreads();

    const int ci = tid >> 5;
    const int px = lane;

    float pre[3][2];
    auto loadCG = [&](int cg) {
        const int c = cg*8 + ci;
        const float* mp = ms + ((size_t)(n*Cc + c))*HW;
#pragma unroll
        for (int r = 0; r < 3; r++) {
            int hh = h + r - 1;
            bool rok = (hh >= 0 && hh < Hh);
            int ww = w0 + lane - 1;
            pre[r][0] = (rok && ww >= 0 && ww < Ww) ? mp[hh*Ww + ww] : 0.f;
            if (lane < 2) {
                int ww2 = w0 + lane + 31;
                pre[r][1] = (rok && ww2 < Ww) ? mp[hh*Ww + ww2] : 0.f;
            }
        }
    };

    loadCG(0);

    for (int cg = 0; cg < 16; cg++) {
#pragma unroll
        for (int r = 0; r < 3; r++) {
            Xs[ci][r][lane] = pre[r][0];
            if (lane < 2) Xs[ci][r][lane + 32] = pre[r][1];
        }
        __syncwarp();

        if (cg + 1 < 16) loadCG(cg + 1);

        const int c = cg*8 + ci;
        float f = 0.f, d = 0.f;
#pragma unroll
        for (int tap = 0; tap < 9; tap++) {
            float xv = Xs[ci][tap/3][px + (tap%3)];
            f += fws[c][tap] * xv;
            d += dks[tap][px] * xv;
        }
        float dynv = fmaxf(d*s2a[c] + t2a[c], 0.f);
        float fixv = fmaxf(f*s1a[c] + t1a[c], 0.f);

        s_cat[px][c]       = __float2half_rn(dynv);
        s_cat[px][128 + c] = __float2half_rn(fixv);
        __syncwarp();
    }
    __syncthreads();

    const int opx = tid >> 3;
    const int sub = tid & 7;
    size_t base = ((size_t)(n*HW) + (size_t)h*Ww + w0 + opx)*256 + sub*32;
    const uint4* sh = (const uint4*)&s_cat[opx][sub*32];
#pragma unroll
    for (int q = 0; q < 4; q++) ((uint4*)(g_cat + base))[q] = sh[q];
}

// ---------------------------------------------------------------------------
// Weight prep: fp16 weights in K-chunked layouts
// ---------------------------------------------------------------------------
__global__ __launch_bounds__(256) void kw_prep(const float* __restrict__ jw)
{
    int idx = blockIdx.x * 256 + threadIdx.x;      // 18*128*64
    if (idx >= 18*128*64) return;
    int cidx = idx >> 13;
    int rr   = idx & 8191;
    int oc   = rr >> 6;
    int k    = rr & 63;
    int tap  = cidx >> 1;
    int ic   = (cidx & 1)*64 + k;
    g_w[idx] = __float2half_rn(jw[oc*(Cc*9) + ic*9 + tap]);
}

__global__ __launch_bounds__(256) void krw_prep(const float* __restrict__ rw)
{
    int idx = blockIdx.x * 256 + threadIdx.x;      // 4*128*64
    if (idx >= 4*128*64) return;
    int ck = idx >> 13;
    int rr = idx & 8191;
    int oc = rr >> 6;
    int k  = rr & 63;
    g_rw[idx] = __float2half_rn(rw[oc*256 + ck*64 + k]);
}

// ---------------------------------------------------------------------------
// K3 smem: 2-stage, A at +0, W at +18432 per stage (R12 layout).
// ---------------------------------------------------------------------------
#define STG_SZ 36864
#define SW_OFF 18432
#define K3_SMEM 73728

__global__ __launch_bounds__(256) void k3_mma(
    const float* __restrict__ coef,
    const float* __restrict__ rb)
{
    extern __shared__ char smem[];
    __shared__ float s_rb[128];
    const int tid = threadIdx.x;
    const int wid = tid >> 5;
    const int lane = tid & 31;
    const int p0 = blockIdx.x * 128;
    const int n  = blockIdx.z;

    if (tid < 128) s_rb[tid] = rb[tid];

    const int r  = tid >> 1;
    const int hf = tid & 1;
    const int wm = (wid & 3) * 32;
    const int wn = (wid >> 2) * 64;
    const int grp = lane >> 2;
    const int t4  = lane & 3;
    const int lr = lane & 7;
    const int lg = lane >> 3;

    const uint32_t smemU = (uint32_t)__cvta_generic_to_shared(smem);
    const uint32_t aRC = (uint32_t)(wm + (lg & 1)*8 + lr)*144 + (lg >> 1)*16;
    const uint32_t bRC = (uint32_t)(wn + (lg >> 1)*8 + lr)*144 + (lg & 1)*16;
    const uint32_t rowOff = (uint32_t)r*144 + hf*64;

    float d[2][8][4];
#pragma unroll
    for (int mf = 0; mf < 2; mf++)
#pragma unroll
        for (int nf = 0; nf < 8; nf++)
#pragma unroll
            for (int q = 0; q < 4; q++) d[mf][nf][q] = 0.f;

    uint4 va[4], vw[4];
    auto loadChunk = [&](int ck) {
        const uint4* pa = (const uint4*)(g_cat + ((size_t)(n*HW) + p0 + r)*256 + ck*64 + hf*32);
        const uint4* pw = (const uint4*)(g_rw + (size_t)ck*8192 + r*64 + hf*32);
#pragma unroll
        for (int q = 0; q < 4; q++) { va[q] = pa[q]; vw[q] = pw[q]; }
    };

    loadChunk(0);

    for (int ck = 0; ck < 4; ck++) {
        const int b = ck & 1;
        char* dst = smem + b*STG_SZ + rowOff;
#pragma unroll
        for (int q = 0; q < 4; q++) {
            *(uint4*)(dst + q*16)          = va[q];
            *(uint4*)(dst + SW_OFF + q*16) = vw[q];
        }
        __syncthreads();

        if (ck + 1 < 4) loadChunk(ck + 1);

        const uint32_t base = smemU + b*STG_SZ;
#pragma unroll
        for (int s = 0; s < 4; s++) {
            const uint32_t kb = s*32;
            uint32_t a[2][4];
#pragma unroll
            for (int mf = 0; mf < 2; mf++)
                ldmat_x4(a[mf], base + aRC + mf*(16*144) + kb);
#pragma unroll
            for (int p = 0; p < 4; p++) {
                uint32_t bw[4];
                ldmat_x4(bw, base + SW_OFF + bRC + p*(16*144) + kb);
#pragma unroll
                for (int e = 0; e < 2; e++) {
                    int nf = 2*p + e;
#pragma unroll
                    for (int mf = 0; mf < 2; mf++)
                        mma16816(d[mf][nf], a[mf], bw[2*e], bw[2*e+1]);
                }
            }
        }
    }

    __syncthreads();
    float* sD = (float*)smem;    // [128 oc][132 px]
#pragma unroll
    for (int mf = 0; mf < 2; mf++)
#pragma unroll
        for (int nf = 0; nf < 8; nf++) {
            int row = wm + mf*16 + grp;
            int col = wn + nf*8 + 2*t4;
            sD[(col  )*132 + row    ] = d[mf][nf][0];
            sD[(col+1)*132 + row    ] = d[mf][nf][1];
            sD[(col  )*132 + row + 8] = d[mf][nf][2];
            sD[(col+1)*132 + row + 8] = d[mf][nf][3];
        }
    __syncthreads();

    const size_t nplane = (size_t)n*Cc*HW;

    {
        const int pxq = (tid & 31) * 4;
#pragma unroll 2
        for (int j = 0; j < 16; j++) {
            int oc = (tid >> 5) + j*8;
            float4 a4 = *(const float4*)&sD[oc*132 + pxq];
            float b = s_rb[oc];
            float4 o = make_float4(a4.x + b, a4.y + b, a4.z + b, a4.w + b);
            *(float4*)(g_fused + nplane + (size_t)oc*HW + p0 + pxq) = o;
        }
    }

    {
        const int px2 = tid >> 1;
        const int half = tid & 1;
#pragma unroll
        for (int jj = 0; jj < 16; jj++) {
            __half hv[4];
#pragma unroll
            for (int e = 0; e < 4; e++) {
                int oc = half*64 + jj*4 + e;
                float v = sD[oc*132 + px2] + s_rb[oc]
                        + coef[nplane + (size_t)oc*HW + p0 + px2];
                hv[e] = __float2half_rn(v);
            }
            size_t dst = ((size_t)(n*HW) + p0 + px2)*128 + half*64 + jj*4;
            *(uint2*)(g_p + dst) = make_uint2(pack_h2(hv[0],hv[1]), pack_h2(hv[2],hv[3]));
        }
    }
}

// ---------------------------------------------------------------------------
// K4 smem: A tiles (130 rows x 144B) double-buffered per (dy,hk) group,
// W chunks (128 rows x 144B) double-buffered per step.
// ---------------------------------------------------------------------------
#define SM_A0 0
#define SM_A1 18720
#define SM_W0 37440
#define SM_W1 55872
#define K4_SMEM 74304

// ---------------------------------------------------------------------------
// K4: joint 3x3 conv, fp16 HMMA implicit GEMM with A-tile reuse across dx:
// 6 groups (dy,hk) x 3 dx-steps; A loaded once per group (130 rows), MMA
// reads shift the A base by dx*144. One barrier per step; reg prefetch.
// ---------------------------------------------------------------------------
__global__ __launch_bounds__(256) void k4_wmma(
    const float* __restrict__ coef,
    const float* __restrict__ jb,
    float* __restrict__ out)
{
    extern __shared__ char smem[];
    const int tid = threadIdx.x;
    const int wid = tid >> 5;
    const int lane = tid & 31;
    const int w0 = blockIdx.x * 128;
    const int h  = blockIdx.y;
    const int n  = blockIdx.z;

    const int r  = tid >> 1;
    const int hf = tid & 1;
    const int wm = (wid & 3) * 32;
    const int wn = (wid >> 2) * 64;
    const int grp = lane >> 2;
    const int t4  = lane & 3;
    const int lr = lane & 7;
    const int lg = lane >> 3;

    const uint32_t smemU = (uint32_t)__cvta_generic_to_shared(smem);
    const uint32_t aRC = (uint32_t)(wm + (lg & 1)*8 + lr)*144 + (lg >> 1)*16;
    const uint32_t bRC = (uint32_t)(wn + (lg >> 1)*8 + lr)*144 + (lg & 1)*16;
    const uint32_t rowOff = (uint32_t)r*144 + hf*64;

    float d[2][8][4];
#pragma unroll
    for (int mf = 0; mf < 2; mf++)
#pragma unroll
        for (int nf = 0; nf < 8; nf++)
#pragma unroll
            for (int q = 0; q < 4; q++) d[mf][nf][q] = 0.f;

    const uint4 z4 = make_uint4(0,0,0,0);
    uint4 va[4], vaE[4], vw[4];
    const bool hasExt = (tid < 4);
    const int rExt = 128 + (tid >> 1);   // rows 128,129 for tid<4

    // load A-tile rows for group g=(dy,hk) into regs
    auto loadA = [&](int g) {
        const int dy = g >> 1;
        const int hk = g & 1;
        const int hh = h + dy - 1;
        {
            const int ww = w0 - 1 + r;
            const bool val = (hh >= 0 && hh < Hh && ww >= 0 && ww < Ww);
            const size_t pix = (size_t)n*HW + (size_t)hh*Ww + ww;
            const uint4* pa = (const uint4*)(g_p + pix*Cc + hk*64 + hf*32);
#pragma unroll
            for (int q = 0; q < 4; q++) va[q] = val ? pa[q] : z4;
        }
        if (hasExt) {
            const int ww = w0 - 1 + rExt;
            const bool val = (hh >= 0 && hh < Hh && ww >= 0 && ww < Ww);
            const size_t pix = (size_t)n*HW + (size_t)hh*Ww + ww;
            const uint4* pa = (const uint4*)(g_p + pix*Cc + hk*64 + hf*32);
#pragma unroll
            for (int q = 0; q < 4; q++) vaE[q] = val ? pa[q] : z4;
        }
    };
    // load W chunk for step
    auto loadW = [&](int step) {
        const int g = step / 3, dx = step - 3*g;
        const int dy = g >> 1, hk = g & 1;
        const int cidx = (dy*3 + dx)*2 + hk;
        const uint4* pw = (const uint4*)(g_w + (size_t)cidx*8192 + r*64 + hf*32);
#pragma unroll
        for (int q = 0; q < 4; q++) vw[q] = pw[q];
    };

    loadA(0);
    loadW(0);

    for (int step = 0; step < 18; step++) {
        const int g  = step / 3;
        const int dx = step - 3*g;
        const uint32_t abuf = (g & 1) ? SM_A1 : SM_A0;
        const uint32_t wbuf = (step & 1) ? SM_W1 : SM_W0;

        if (dx == 0) {
            char* dstA = smem + abuf + rowOff;
#pragma unroll
            for (int q = 0; q < 4; q++) *(uint4*)(dstA + q*16) = va[q];
            if (hasExt) {
                char* dstE = smem + abuf + (uint32_t)rExt*144 + hf*64;
#pragma unroll
                for (int q = 0; q < 4; q++) *(uint4*)(dstE + q*16) = vaE[q];
            }
        }
        {
            char* dstW = smem + wbuf + rowOff;
#pragma unroll
            for (int q = 0; q < 4; q++) *(uint4*)(dstW + q*16) = vw[q];
        }
        __syncthreads();

        if (step + 1 < 18) {
            loadW(step + 1);
            if (dx == 2) loadA(g + 1);
        }

        const uint32_t baseA = smemU + abuf + (uint32_t)dx*144;
        const uint32_t baseW = smemU + wbuf;
#pragma unroll
        for (int s = 0; s < 4; s++) {
            const uint32_t kb = s*32;
            uint32_t a[2][4];
#pragma unroll
            for (int mf = 0; mf < 2; mf++)
                ldmat_x4(a[mf], baseA + aRC + mf*(16*144) + kb);
#pragma unroll
            for (int p = 0; p < 4; p++) {
                uint32_t bw[4];
                ldmat_x4(bw, baseW + bRC + p*(16*144) + kb);
#pragma unroll
                for (int e = 0; e < 2; e++) {
                    int nf = 2*p + e;
#pragma unroll
                    for (int mf = 0; mf < 2; mf++)
                        mma16816(d[mf][nf], a[mf], bw[2*e], bw[2*e+1]);
                }
            }
        }
    }

    __syncthreads();
    float* sD = (float*)smem;
#pragma unroll
    for (int mf = 0; mf < 2; mf++)
#pragma unroll
        for (int nf = 0; nf < 8; nf++) {
            int row = wm + mf*16 + grp;
            int col = wn + nf*8 + 2*t4;
            sD[(col  )*132 + row    ] = d[mf][nf][0];
            sD[(col+1)*132 + row    ] = d[mf][nf][1];
            sD[(col  )*132 + row + 8] = d[mf][nf][2];
            sD[(col+1)*132 + row + 8] = d[mf][nf][3];
        }
    __syncthreads();

    const size_t nplane = (size_t)n*Cc*HW;
    const int px = (tid & 31) * 4;
#pragma unroll 2
    for (int j = 0; j < 16; j++) {
        int oc = (tid >> 5) + j*8;
        float4 a4 = *(const float4*)&sD[oc*132 + px];
        float b = jb[oc];
        size_t base = nplane + (size_t)oc*HW + (size_t)h*Ww + w0 + px;
        float4 fu = *(const float4*)&g_fused[base];
        float4 cf = *(const float4*)&coef[base];
        float4 o;
        { float p2 = 1.f/(1.f + __expf(-(a4.x + b))); o.x = fu.x + p2*(cf.x - fu.x); }
        { float p2 = 1.f/(1.f + __expf(-(a4.y + b))); o.y = fu.y + p2*(cf.y - fu.y); }
        { float p2 = 1.f/(1.f + __expf(-(a4.z + b))); o.z = fu.z + p2*(cf.z - fu.z); }
        { float p2 = 1.f/(1.f + __expf(-(a4.w + b))); o.w = fu.w + p2*(cf.w - fu.w); }
        *(float4*)(out + base) = o;
    }
}

// ---------------------------------------------------------------------------
extern "C" void kernel_launch(void* const* d_in, const int* in_sizes, int n_in,
                              void* d_out, int out_size)
{
    const float* coef  = (const float*)d_in[0];
    const float* ms    = (const float*)d_in[1];
    const float* fix_w = (const float*)d_in[2];
    const float* bn1_g = (const float*)d_in[3];
    const float* bn1_b = (const float*)d_in[4];
    const float* bn1_m = (const float*)d_in[5];
    const float* bn1_v = (const float*)d_in[6];
    const float* dyn_w = (const float*)d_in[7];
    const float* dyn_b = (const float*)d_in[8];
    const float* bn2_g = (const float*)d_in[9];
    const float* bn2_b = (const float*)d_in[10];
    const float* bn2_m = (const float*)d_in[11];
    const float* bn2_v = (const float*)d_in[12];
    const float* refine_w = (const float*)d_in[13];
    const float* refine_b = (const float*)d_in[14];
    const float* joint_w  = (const float*)d_in[15];
    const float* joint_b  = (const float*)d_in[16];
    float* outp = (float*)d_out;

    cudaFuncSetAttribute(k3_mma,  cudaFuncAttributeMaxDynamicSharedMemorySize, K3_SMEM);
    cudaFuncSetAttribute(k4_wmma, cudaFuncAttributeMaxDynamicSharedMemorySize, K4_SMEM);

    kw_prep<<<(18*128*64 + 255)/256, 256>>>(joint_w);
    krw_prep<<<(4*128*64 + 255)/256, 256>>>(refine_w);
    k1_dynkernel<<<dim3(Ww/128, Hh, Nn), 128>>>(ms, dyn_w, dyn_b);
    k2_cat_nhwc<<<dim3(Ww/32, Hh, Nn), 256>>>(ms, fix_w,
                                              bn1_g, bn1_b, bn1_m, bn1_v,
                                              bn2_g, bn2_b, bn2_m, bn2_v);
    k3_mma<<<dim3(HW/128, 1, Nn), 256, K3_SMEM>>>(coef, refine_b);
    k4_wmma<<<dim3(Ww/128, Hh, Nn), 256, K4_SMEM>>>(coef, joint_b, outp);
}

// round 16
// speedup vs baseline: 1.0838x; 1.0838x over previous
#include <cuda_runtime.h>
#include <cuda_fp16.h>
#include <cstdint>

#define Nn 4
#define Cc 128
#define Hh 256
#define Ww 256
#define HW (Hh*Ww)

// ---------------- scratch (device globals; allocation-free) ----------------
__device__ float g_dk[(size_t)Nn*9*HW];                        // dyn kernels
__device__ float g_fused[(size_t)Nn*Cc*HW];                    // refine out NCHW
__device__ __align__(256) __half g_cat[(size_t)Nn*HW*256];     // cat NHWC fp16
__device__ __align__(256) __half g_p  [(size_t)Nn*HW*Cc];      // p NHWC fp16
__device__ __align__(256) __half g_w  [18*128*64];             // joint W fp16
__device__ __align__(256) __half g_rw [4*128*64];              // refine W fp16

// ---------------------------------------------------------------------------
__device__ __forceinline__ void mma16816(float* d, const uint32_t* a,
                                         uint32_t b0, uint32_t b1) {
    asm volatile(
        "mma.sync.aligned.m16n8k16.row.col.f32.f16.f16.f32 "
        "{%0,%1,%2,%3}, {%4,%5,%6,%7}, {%8,%9}, {%0,%1,%2,%3};"
        : "+f"(d[0]), "+f"(d[1]), "+f"(d[2]), "+f"(d[3])
        : "r"(a[0]), "r"(a[1]), "r"(a[2]), "r"(a[3]), "r"(b0), "r"(b1));
}
__device__ __forceinline__ void ldmat_x4(uint32_t* r, uint32_t saddr) {
    asm volatile("ldmatrix.sync.aligned.m8n8.x4.shared.b16 {%0,%1,%2,%3}, [%4];"
        : "=r"(r[0]), "=r"(r[1]), "=r"(r[2]), "=r"(r[3]) : "r"(saddr));
}
__device__ __forceinline__ uint32_t pack_h2(__half a, __half b) {
    __half2 h2; h2.x = a; h2.y = b;
    return *(uint32_t*)&h2;
}

// ---------------------------------------------------------------------------
// K1: dyn_kernel conv(ms, dyn_w[9,128,3,3]) + b, L1-normalized over 9 taps.
// Transposed weight tile, float4 weight loads (R12).
// ---------------------------------------------------------------------------
__global__ __launch_bounds__(128) void k1_dynkernel(
    const float* __restrict__ ms,
    const float* __restrict__ dyn_w,
    const float* __restrict__ dyn_b)
{
    const int w0 = blockIdx.x * 128;
    const int h  = blockIdx.y;
    const int n  = blockIdx.z;
    const int tid = threadIdx.x;

    __shared__ float Xs[3][130];
    __shared__ __align__(16) float Wt[9][12];   // [tap][k], 48B rows

    float acc[9];
#pragma unroll
    for (int k = 0; k < 9; k++) acc[k] = dyn_b[k];

    for (int ic = 0; ic < Cc; ic++) {
        const float* mp = ms + ((size_t)(n*Cc + ic))*HW;
        for (int idx = tid; idx < 3*130; idx += 128) {
            int r = idx / 130, cc2 = idx % 130;
            int hh = h + r - 1, ww = w0 + cc2 - 1;
            float v = 0.f;
            if (hh >= 0 && hh < Hh && ww >= 0 && ww < Ww) v = mp[hh*Ww + ww];
            Xs[r][cc2] = v;
        }
        if (tid < 81)
            Wt[tid%9][tid/9] = dyn_w[(tid/9)*(Cc*9) + ic*9 + (tid%9)];
        __syncthreads();

#pragma unroll
        for (int tap = 0; tap < 9; tap++) {
            float xv = Xs[tap/3][tid + (tap%3)];
            float4 wa = *(const float4*)&Wt[tap][0];
            float4 wb = *(const float4*)&Wt[tap][4];
            float w8  = Wt[tap][8];
            acc[0] += wa.x*xv; acc[1] += wa.y*xv; acc[2] += wa.z*xv; acc[3] += wa.w*xv;
            acc[4] += wb.x*xv; acc[5] += wb.y*xv; acc[6] += wb.z*xv; acc[7] += wb.w*xv;
            acc[8] += w8*xv;
        }
        __syncthreads();
    }

    float denom = 0.f;
#pragma unroll
    for (int k = 0; k < 9; k++) denom += fabsf(acc[k]);
    float inv = 1.f / denom;
#pragma unroll
    for (int k = 0; k < 9; k++)
        g_dk[((size_t)(n*9 + k))*HW + (size_t)h*Ww + w0 + tid] = acc[k] * inv;
}

// ---------------------------------------------------------------------------
// K2: concat tensor in NHWC fp16. Warp-private tiles, register-prefetched
// halo loads; fws rows padded to 12 floats for float4 loads.
// ---------------------------------------------------------------------------
__global__ __launch_bounds__(256) void k2_cat_nhwc(
    const float* __restrict__ ms,
    const float* __restrict__ fix_w,
    const float* __restrict__ bn1_g, const float* __restrict__ bn1_b,
    const float* __restrict__ bn1_m, const float* __restrict__ bn1_v,
    const float* __restrict__ bn2_g, const float* __restrict__ bn2_b,
    const float* __restrict__ bn2_m, const float* __restrict__ bn2_v)
{
    const int w0 = blockIdx.x * 32;
    const int h  = blockIdx.y;
    const int n  = blockIdx.z;
    const int tid = threadIdx.x;
    const int lane = tid & 31;

    __shared__ float dks[9][32];
    __shared__ float Xs[8][3][34];
    __shared__ float s1a[128], t1a[128], s2a[128], t2a[128];
    __shared__ __align__(16) float fws[128][12];
    __shared__ __half s_cat[32][264];

    if (tid < 128) {
        float s1 = bn1_g[tid] * rsqrtf(bn1_v[tid] + 1e-5f);
        s1a[tid] = s1; t1a[tid] = bn1_b[tid] - bn1_m[tid]*s1;
        float s2 = bn2_g[tid] * rsqrtf(bn2_v[tid] + 1e-5f);
        s2a[tid] = s2; t2a[tid] = bn2_b[tid] - bn2_m[tid]*s2;
    }
    for (int idx = tid; idx < 1152; idx += 256)
        fws[idx/9][idx%9] = fix_w[idx];
    for (int idx = tid; idx < 288; idx += 256) {
        int tap = idx >> 5, px = idx & 31;
        dks[tap][px] = g_dk[((size_t)(n*9 + tap))*HW + (size_t)h*Ww + w0 + px];
    }
    __syncthreads();

    const int ci = tid >> 5;
    const int px = lane;

    float pre[3][2];
    auto loadCG = [&](int cg) {
        const int c = cg*8 + ci;
        const float* mp = ms + ((size_t)(n*Cc + c))*HW;
#pragma unroll
        for (int r = 0; r < 3; r++) {
            int hh = h + r - 1;
            bool rok = (hh >= 0 && hh < Hh);
            int ww = w0 + lane - 1;
            pre[r][0] = (rok && ww >= 0 && ww < Ww) ? mp[hh*Ww + ww] : 0.f;
            if (lane < 2) {
                int ww2 = w0 + lane + 31;
                pre[r][1] = (rok && ww2 < Ww) ? mp[hh*Ww + ww2] : 0.f;
            }
        }
    };

    loadCG(0);

    for (int cg = 0; cg < 16; cg++) {
#pragma unroll
        for (int r = 0; r < 3; r++) {
            Xs[ci][r][lane] = pre[r][0];
            if (lane < 2) Xs[ci][r][lane + 32] = pre[r][1];
        }
        __syncwarp();

        if (cg + 1 < 16) loadCG(cg + 1);

        const int c = cg*8 + ci;
        float4 wa = *(const float4*)&fws[c][0];
        float4 wb = *(const float4*)&fws[c][4];
        float w8  = fws[c][8];
        float wreg[9] = {wa.x, wa.y, wa.z, wa.w, wb.x, wb.y, wb.z, wb.w, w8};

        float f = 0.f, d = 0.f;
#pragma unroll
        for (int tap = 0; tap < 9; tap++) {
            float xv = Xs[ci][tap/3][px + (tap%3)];
            f += wreg[tap] * xv;
            d += dks[tap][px] * xv;
        }
        float dynv = fmaxf(d*s2a[c] + t2a[c], 0.f);
        float fixv = fmaxf(f*s1a[c] + t1a[c], 0.f);

        s_cat[px][c]       = __float2half_rn(dynv);
        s_cat[px][128 + c] = __float2half_rn(fixv);
        __syncwarp();
    }
    __syncthreads();

    const int opx = tid >> 3;
    const int sub = tid & 7;
    size_t base = ((size_t)(n*HW) + (size_t)h*Ww + w0 + opx)*256 + sub*32;
    const uint4* sh = (const uint4*)&s_cat[opx][sub*32];
#pragma unroll
    for (int q = 0; q < 4; q++) ((uint4*)(g_cat + base))[q] = sh[q];
}

// ---------------------------------------------------------------------------
// Weight prep: fp16 weights in K-chunked layouts
// ---------------------------------------------------------------------------
__global__ __launch_bounds__(256) void kw_prep(const float* __restrict__ jw)
{
    int idx = blockIdx.x * 256 + threadIdx.x;      // 18*128*64
    if (idx >= 18*128*64) return;
    int cidx = idx >> 13;
    int rr   = idx & 8191;
    int oc   = rr >> 6;
    int k    = rr & 63;
    int tap  = cidx >> 1;
    int ic   = (cidx & 1)*64 + k;
    g_w[idx] = __float2half_rn(jw[oc*(Cc*9) + ic*9 + tap]);
}

__global__ __launch_bounds__(256) void krw_prep(const float* __restrict__ rw)
{
    int idx = blockIdx.x * 256 + threadIdx.x;      // 4*128*64
    if (idx >= 4*128*64) return;
    int ck = idx >> 13;
    int rr = idx & 8191;
    int oc = rr >> 6;
    int k  = rr & 63;
    g_rw[idx] = __float2half_rn(rw[oc*256 + ck*64 + k]);
}

// ---------------------------------------------------------------------------
// GEMM smem: 2-stage, A at +0, W at +18432 per stage; 144B rows, one barrier
// per chunk (R12 layout).
// ---------------------------------------------------------------------------
#define STG_SZ 36864
#define SW_OFF 18432
#define GEMM_SMEM 73728

// ---------------------------------------------------------------------------
// K3: refine 1x1 as fp16 HMMA GEMM (K=256, 4 chunks).
// Epilogue: g_fused (NCHW fp32) + p=fused+coef -> g_p (NHWC fp16).
// ---------------------------------------------------------------------------
__global__ __launch_bounds__(256) void k3_mma(
    const float* __restrict__ coef,
    const float* __restrict__ rb)
{
    extern __shared__ char smem[];
    __shared__ float s_rb[128];
    const int tid = threadIdx.x;
    const int wid = tid >> 5;
    const int lane = tid & 31;
    const int p0 = blockIdx.x * 128;
    const int n  = blockIdx.z;

    if (tid < 128) s_rb[tid] = rb[tid];

    const int r  = tid >> 1;
    const int hf = tid & 1;
    const int wm = (wid & 3) * 32;
    const int wn = (wid >> 2) * 64;
    const int grp = lane >> 2;
    const int t4  = lane & 3;
    const int lr = lane & 7;
    const int lg = lane >> 3;

    const uint32_t smemU = (uint32_t)__cvta_generic_to_shared(smem);
    const uint32_t aRC = (uint32_t)(wm + (lg & 1)*8 + lr)*144 + (lg >> 1)*16;
    const uint32_t bRC = (uint32_t)(wn + (lg >> 1)*8 + lr)*144 + (lg & 1)*16;
    const uint32_t rowOff = (uint32_t)r*144 + hf*64;

    float d[2][8][4];
#pragma unroll
    for (int mf = 0; mf < 2; mf++)
#pragma unroll
        for (int nf = 0; nf < 8; nf++)
#pragma unroll
            for (int q = 0; q < 4; q++) d[mf][nf][q] = 0.f;

    uint4 va[4], vw[4];
    auto loadChunk = [&](int ck) {
        const uint4* pa = (const uint4*)(g_cat + ((size_t)(n*HW) + p0 + r)*256 + ck*64 + hf*32);
        const uint4* pw = (const uint4*)(g_rw + (size_t)ck*8192 + r*64 + hf*32);
#pragma unroll
        for (int q = 0; q < 4; q++) { va[q] = pa[q]; vw[q] = pw[q]; }
    };

    loadChunk(0);

    for (int ck = 0; ck < 4; ck++) {
        const int b = ck & 1;
        char* dst = smem + b*STG_SZ + rowOff;
#pragma unroll
        for (int q = 0; q < 4; q++) {
            *(uint4*)(dst + q*16)          = va[q];
            *(uint4*)(dst + SW_OFF + q*16) = vw[q];
        }
        __syncthreads();

        if (ck + 1 < 4) loadChunk(ck + 1);

        const uint32_t base = smemU + b*STG_SZ;
#pragma unroll
        for (int s = 0; s < 4; s++) {
            const uint32_t kb = s*32;
            uint32_t a[2][4];
#pragma unroll
            for (int mf = 0; mf < 2; mf++)
                ldmat_x4(a[mf], base + aRC + mf*(16*144) + kb);
#pragma unroll
            for (int p = 0; p < 4; p++) {
                uint32_t bw[4];
                ldmat_x4(bw, base + SW_OFF + bRC + p*(16*144) + kb);
#pragma unroll
                for (int e = 0; e < 2; e++) {
                    int nf = 2*p + e;
#pragma unroll
                    for (int mf = 0; mf < 2; mf++)
                        mma16816(d[mf][nf], a[mf], bw[2*e], bw[2*e+1]);
                }
            }
        }
    }

    __syncthreads();
    float* sD = (float*)smem;    // [128 oc][132 px]
#pragma unroll
    for (int mf = 0; mf < 2; mf++)
#pragma unroll
        for (int nf = 0; nf < 8; nf++) {
            int row = wm + mf*16 + grp;
            int col = wn + nf*8 + 2*t4;
            sD[(col  )*132 + row    ] = d[mf][nf][0];
            sD[(col+1)*132 + row    ] = d[mf][nf][1];
            sD[(col  )*132 + row + 8] = d[mf][nf][2];
            sD[(col+1)*132 + row + 8] = d[mf][nf][3];
        }
    __syncthreads();

    const size_t nplane = (size_t)n*Cc*HW;

    {
        const int pxq = (tid & 31) * 4;
#pragma unroll 2
        for (int j = 0; j < 16; j++) {
            int oc = (tid >> 5) + j*8;
            float4 a4 = *(const float4*)&sD[oc*132 + pxq];
            float b = s_rb[oc];
            float4 o = make_float4(a4.x + b, a4.y + b, a4.z + b, a4.w + b);
            *(float4*)(g_fused + nplane + (size_t)oc*HW + p0 + pxq) = o;
        }
    }

    {
        const int px2 = tid >> 1;
        const int half = tid & 1;
#pragma unroll
        for (int jj = 0; jj < 16; jj++) {
            __half hv[4];
#pragma unroll
            for (int e = 0; e < 4; e++) {
                int oc = half*64 + jj*4 + e;
                float v = sD[oc*132 + px2] + s_rb[oc]
                        + coef[nplane + (size_t)oc*HW + p0 + px2];
                hv[e] = __float2half_rn(v);
            }
            size_t dst = ((size_t)(n*HW) + p0 + px2)*128 + half*64 + jj*4;
            *(uint2*)(g_p + dst) = make_uint2(pack_h2(hv[0],hv[1]), pack_h2(hv[2],hv[3]));
        }
    }
}

// ---------------------------------------------------------------------------
// K4: joint 3x3 conv as fp16 HMMA implicit GEMM, double-buffered (1 barrier
// per chunk), register prefetch + sigmoid-gating epilogue (R12).
// ---------------------------------------------------------------------------
__global__ __launch_bounds__(256) void k4_wmma(
    const float* __restrict__ coef,
    const float* __restrict__ jb,
    float* __restrict__ out)
{
    extern __shared__ char smem[];
    const int tid = threadIdx.x;
    const int wid = tid >> 5;
    const int lane = tid & 31;
    const int w0 = blockIdx.x * 128;
    const int h  = blockIdx.y;
    const int n  = blockIdx.z;

    const int r  = tid >> 1;
    const int hf = tid & 1;
    const int wm = (wid & 3) * 32;
    const int wn = (wid >> 2) * 64;
    const int grp = lane >> 2;
    const int t4  = lane & 3;
    const int lr = lane & 7;
    const int lg = lane >> 3;

    const uint32_t smemU = (uint32_t)__cvta_generic_to_shared(smem);
    const uint32_t aRC = (uint32_t)(wm + (lg & 1)*8 + lr)*144 + (lg >> 1)*16;
    const uint32_t bRC = (uint32_t)(wn + (lg >> 1)*8 + lr)*144 + (lg & 1)*16;
    const uint32_t rowOff = (uint32_t)r*144 + hf*64;

    float d[2][8][4];
#pragma unroll
    for (int mf = 0; mf < 2; mf++)
#pragma unroll
        for (int nf = 0; nf < 8; nf++)
#pragma unroll
            for (int q = 0; q < 4; q++) d[mf][nf][q] = 0.f;

    const uint4 z4 = make_uint4(0,0,0,0);
    uint4 va[4], vw[4];

    auto loadChunk = [&](int cidx) {
        const int tap = cidx >> 1;
        const int hk  = cidx & 1;
        const int dy = tap / 3, dx = tap % 3;
        const int hh = h + dy - 1;
        const int ww = w0 + dx - 1 + r;
        const bool val = (hh >= 0 && hh < Hh && ww >= 0 && ww < Ww);
        const size_t pix = (size_t)n*HW + (size_t)hh*Ww + ww;
        const uint4* pa = (const uint4*)(g_p + pix*Cc + hk*64 + hf*32);
        const uint4* pw = (const uint4*)(g_w + (size_t)cidx*8192 + r*64 + hf*32);
#pragma unroll
        for (int q = 0; q < 4; q++) {
            va[q] = val ? pa[q] : z4;
            vw[q] = pw[q];
        }
    };

    loadChunk(0);

    for (int cidx = 0; cidx < 18; cidx++) {
        const int b = cidx & 1;
        char* dst = smem + b*STG_SZ + rowOff;
#pragma unroll
        for (int q = 0; q < 4; q++) {
            *(uint4*)(dst + q*16)          = va[q];
            *(uint4*)(dst + SW_OFF + q*16) = vw[q];
        }
        __syncthreads();

        if (cidx + 1 < 18) loadChunk(cidx + 1);

        const uint32_t base = smemU + b*STG_SZ;
#pragma unroll
        for (int s = 0; s < 4; s++) {
            const uint32_t kb = s*32;
            uint32_t a[2][4];
#pragma unroll
            for (int mf = 0; mf < 2; mf++)
                ldmat_x4(a[mf], base + aRC + mf*(16*144) + kb);
#pragma unroll
            for (int p = 0; p < 4; p++) {
                uint32_t bw[4];
                ldmat_x4(bw, base + SW_OFF + bRC + p*(16*144) + kb);
#pragma unroll
                for (int e = 0; e < 2; e++) {
                    int nf = 2*p + e;
#pragma unroll
                    for (int mf = 0; mf < 2; mf++)
                        mma16816(d[mf][nf], a[mf], bw[2*e], bw[2*e+1]);
                }
            }
        }
    }

    __syncthreads();
    float* sD = (float*)smem;
#pragma unroll
    for (int mf = 0; mf < 2; mf++)
#pragma unroll
        for (int nf = 0; nf < 8; nf++) {
            int row = wm + mf*16 + grp;
            int col = wn + nf*8 + 2*t4;
            sD[(col  )*132 + row    ] = d[mf][nf][0];
            sD[(col+1)*132 + row    ] = d[mf][nf][1];
            sD[(col  )*132 + row + 8] = d[mf][nf][2];
            sD[(col+1)*132 + row + 8] = d[mf][nf][3];
        }
    __syncthreads();

    const size_t nplane = (size_t)n*Cc*HW;
    const int px = (tid & 31) * 4;
#pragma unroll 2
    for (int j = 0; j < 16; j++) {
        int oc = (tid >> 5) + j*8;
        float4 a4 = *(const float4*)&sD[oc*132 + px];
        float b = jb[oc];
        size_t base = nplane + (size_t)oc*HW + (size_t)h*Ww + w0 + px;
        float4 fu = *(const float4*)&g_fused[base];
        float4 cf = *(const float4*)&coef[base];
        float4 o;
        { float p2 = 1.f/(1.f + __expf(-(a4.x + b))); o.x = fu.x + p2*(cf.x - fu.x); }
        { float p2 = 1.f/(1.f + __expf(-(a4.y + b))); o.y = fu.y + p2*(cf.y - fu.y); }
        { float p2 = 1.f/(1.f + __expf(-(a4.z + b))); o.z = fu.z + p2*(cf.z - fu.z); }
        { float p2 = 1.f/(1.f + __expf(-(a4.w + b))); o.w = fu.w + p2*(cf.w - fu.w); }
        *(float4*)(out + base) = o;
    }
}

// ---------------------------------------------------------------------------
extern "C" void kernel_launch(void* const* d_in, const int* in_sizes, int n_in,
                              void* d_out, int out_size)
{
    const float* coef  = (const float*)d_in[0];
    const float* ms    = (const float*)d_in[1];
    const float* fix_w = (const float*)d_in[2];
    const float* bn1_g = (const float*)d_in[3];
    const float* bn1_b = (const float*)d_in[4];
    const float* bn1_m = (const float*)d_in[5];
    const float* bn1_v = (const float*)d_in[6];
    const float* dyn_w = (const float*)d_in[7];
    const float* dyn_b = (const float*)d_in[8];
    const float* bn2_g = (const float*)d_in[9];
    const float* bn2_b = (const float*)d_in[10];
    const float* bn2_m = (const float*)d_in[11];
    const float* bn2_v = (const float*)d_in[12];
    const float* refine_w = (const float*)d_in[13];
    const float* refine_b = (const float*)d_in[14];
    const float* joint_w  = (const float*)d_in[15];
    const float* joint_b  = (const float*)d_in[16];
    float* outp = (float*)d_out;

    cudaFuncSetAttribute(k3_mma,  cudaFuncAttributeMaxDynamicSharedMemorySize, GEMM_SMEM);
    cudaFuncSetAttribute(k4_wmma, cudaFuncAttributeMaxDynamicSharedMemorySize, GEMM_SMEM);

    kw_prep<<<(18*128*64 + 255)/256, 256>>>(joint_w);
    krw_prep<<<(4*128*64 + 255)/256, 256>>>(refine_w);
    k1_dynkernel<<<dim3(Ww/128, Hh, Nn), 128>>>(ms, dyn_w, dyn_b);
    k2_cat_nhwc<<<dim3(Ww/32, Hh, Nn), 256>>>(ms, fix_w,
                                              bn1_g, bn1_b, bn1_m, bn1_v,
                                              bn2_g, bn2_b, bn2_m, bn2_v);
    k3_mma<<<dim3(HW/128, 1, Nn), 256, GEMM_SMEM>>>(coef, refine_b);
    k4_wmma<<<dim3(Ww/128, Hh, Nn), 256, GEMM_SMEM>>>(coef, joint_b, outp);
}

// round 17
// speedup vs baseline: 1.1604x; 1.0708x over previous
#include <cuda_runtime.h>
#include <cuda_fp16.h>
#include <cstdint>

#define Nn 4
#define Cc 128
#define Hh 256
#define Ww 256
#define HW (Hh*Ww)

// ---------------- scratch (device globals; allocation-free) ----------------
__device__ float g_dk[(size_t)Nn*9*HW];                        // dyn kernels
__device__ float g_fused[(size_t)Nn*Cc*HW];                    // refine out NCHW
__device__ __align__(256) __half g_cat[(size_t)Nn*HW*256];     // cat NHWC fp16
__device__ __align__(256) __half g_p  [(size_t)Nn*HW*Cc];      // p NHWC fp16
__device__ __align__(256) __half g_w  [18*128*64];             // joint W fp16
__device__ __align__(256) __half g_rw [4*128*64];              // refine W fp16

// ---------------------------------------------------------------------------
__device__ __forceinline__ void mma16816(float* d, const uint32_t* a,
                                         uint32_t b0, uint32_t b1) {
    asm volatile(
        "mma.sync.aligned.m16n8k16.row.col.f32.f16.f16.f32 "
        "{%0,%1,%2,%3}, {%4,%5,%6,%7}, {%8,%9}, {%0,%1,%2,%3};"
        : "+f"(d[0]), "+f"(d[1]), "+f"(d[2]), "+f"(d[3])
        : "r"(a[0]), "r"(a[1]), "r"(a[2]), "r"(a[3]), "r"(b0), "r"(b1));
}
__device__ __forceinline__ void ldmat_x4(uint32_t* r, uint32_t saddr) {
    asm volatile("ldmatrix.sync.aligned.m8n8.x4.shared.b16 {%0,%1,%2,%3}, [%4];"
        : "=r"(r[0]), "=r"(r[1]), "=r"(r[2]), "=r"(r[3]) : "r"(saddr));
}
__device__ __forceinline__ uint32_t pack_h2(__half a, __half b) {
    __half2 h2; h2.x = a; h2.y = b;
    return *(uint32_t*)&h2;
}

// ---------------------------------------------------------------------------
// K1: dyn_kernel conv(ms, dyn_w[9,128,3,3]) + b, L1-normalized over 9 taps.
// Double-buffered Xs/Wt (one barrier per ic) + register-prefetched halo loads
// with loop-invariant offsets.
// ---------------------------------------------------------------------------
__global__ __launch_bounds__(128) void k1_dynkernel(
    const float* __restrict__ ms,
    const float* __restrict__ dyn_w,
    const float* __restrict__ dyn_b)
{
    const int w0 = blockIdx.x * 128;
    const int h  = blockIdx.y;
    const int n  = blockIdx.z;
    const int tid = threadIdx.x;

    __shared__ float Xs[2][3][130];
    __shared__ __align__(16) float Wt[2][9][12];   // [tap][k], 48B rows

    // loop-invariant halo slot descriptors (3 slots/thread, 4th for tid<6)
    int soff[4], srow[4], scol[4];
    bool svld[4];
#pragma unroll
    for (int j = 0; j < 4; j++) {
        int idx = tid + j*128;
        if (idx < 390) {
            int r = idx / 130, cc2 = idx % 130;
            int hh = h + r - 1, ww = w0 + cc2 - 1;
            svld[j] = (hh >= 0 && hh < Hh && ww >= 0 && ww < Ww);
            soff[j] = svld[j] ? (hh*Ww + ww) : 0;
            srow[j] = r; scol[j] = cc2;
        } else {
            svld[j] = false; soff[j] = 0; srow[j] = 0; scol[j] = 0;
        }
    }
    const bool hasW = (tid < 81);
    const float* wbase = dyn_w + (tid/9)*(Cc*9) + (tid%9);
    const float* msn = ms + (size_t)(n*Cc)*HW;

    float pre[4]; float wpre = 0.f;
    auto loadIC = [&](int ic) {
        const float* mp = msn + (size_t)ic*HW;
        pre[0] = svld[0] ? mp[soff[0]] : 0.f;
        pre[1] = svld[1] ? mp[soff[1]] : 0.f;
        pre[2] = svld[2] ? mp[soff[2]] : 0.f;
        if (tid < 6) pre[3] = svld[3] ? mp[soff[3]] : 0.f;
        if (hasW) wpre = wbase[ic*9];
    };

    float acc[9];
#pragma unroll
    for (int k = 0; k < 9; k++) acc[k] = dyn_b[k];

    loadIC(0);

    for (int ic = 0; ic < Cc; ic++) {
        const int b = ic & 1;
        Xs[b][srow[0]][scol[0]] = pre[0];
        Xs[b][srow[1]][scol[1]] = pre[1];
        Xs[b][srow[2]][scol[2]] = pre[2];
        if (tid < 6) Xs[b][srow[3]][scol[3]] = pre[3];
        if (hasW) Wt[b][tid%9][tid/9] = wpre;
        __syncthreads();

        if (ic + 1 < Cc) loadIC(ic + 1);   // overlaps FFMAs below

#pragma unroll
        for (int tap = 0; tap < 9; tap++) {
            float xv = Xs[b][tap/3][tid + (tap%3)];
            float4 wa = *(const float4*)&Wt[b][tap][0];
            float4 wb = *(const float4*)&Wt[b][tap][4];
            float w8  = Wt[b][tap][8];
            acc[0] += wa.x*xv; acc[1] += wa.y*xv; acc[2] += wa.z*xv; acc[3] += wa.w*xv;
            acc[4] += wb.x*xv; acc[5] += wb.y*xv; acc[6] += wb.z*xv; acc[7] += wb.w*xv;
            acc[8] += w8*xv;
        }
    }

    float denom = 0.f;
#pragma unroll
    for (int k = 0; k < 9; k++) denom += fabsf(acc[k]);
    float inv = 1.f / denom;
#pragma unroll
    for (int k = 0; k < 9; k++)
        g_dk[((size_t)(n*9 + k))*HW + (size_t)h*Ww + w0 + tid] = acc[k] * inv;
}

// ---------------------------------------------------------------------------
// K2: concat tensor in NHWC fp16. Warp-private tiles, register-prefetched
// halo loads; fws rows padded to 12 floats for float4 loads.
// ---------------------------------------------------------------------------
__global__ __launch_bounds__(256) void k2_cat_nhwc(
    const float* __restrict__ ms,
    const float* __restrict__ fix_w,
    const float* __restrict__ bn1_g, const float* __restrict__ bn1_b,
    const float* __restrict__ bn1_m, const float* __restrict__ bn1_v,
    const float* __restrict__ bn2_g, const float* __restrict__ bn2_b,
    const float* __restrict__ bn2_m, const float* __restrict__ bn2_v)
{
    const int w0 = blockIdx.x * 32;
    const int h  = blockIdx.y;
    const int n  = blockIdx.z;
    const int tid = threadIdx.x;
    const int lane = tid & 31;

    __shared__ float dks[9][32];
    __shared__ float Xs[8][3][34];
    __shared__ float s1a[128], t1a[128], s2a[128], t2a[128];
    __shared__ __align__(16) float fws[128][12];
    __shared__ __half s_cat[32][264];

    if (tid < 128) {
        float s1 = bn1_g[tid] * rsqrtf(bn1_v[tid] + 1e-5f);
        s1a[tid] = s1; t1a[tid] = bn1_b[tid] - bn1_m[tid]*s1;
        float s2 = bn2_g[tid] * rsqrtf(bn2_v[tid] + 1e-5f);
        s2a[tid] = s2; t2a[tid] = bn2_b[tid] - bn2_m[tid]*s2;
    }
    for (int idx = tid; idx < 1152; idx += 256)
        fws[idx/9][idx%9] = fix_w[idx];
    for (int idx = tid; idx < 288; idx += 256) {
        int tap = idx >> 5, px = idx & 31;
        dks[tap][px] = g_dk[((size_t)(n*9 + tap))*HW + (size_t)h*Ww + w0 + px];
    }
    __syncthreads();

    const int ci = tid >> 5;
    const int px = lane;

    float pre[3][2];
    auto loadCG = [&](int cg) {
        const int c = cg*8 + ci;
        const float* mp = ms + ((size_t)(n*Cc + c))*HW;
#pragma unroll
        for (int r = 0; r < 3; r++) {
            int hh = h + r - 1;
            bool rok = (hh >= 0 && hh < Hh);
            int ww = w0 + lane - 1;
            pre[r][0] = (rok && ww >= 0 && ww < Ww) ? mp[hh*Ww + ww] : 0.f;
            if (lane < 2) {
                int ww2 = w0 + lane + 31;
                pre[r][1] = (rok && ww2 < Ww) ? mp[hh*Ww + ww2] : 0.f;
            }
        }
    };

    loadCG(0);

    for (int cg = 0; cg < 16; cg++) {
#pragma unroll
        for (int r = 0; r < 3; r++) {
            Xs[ci][r][lane] = pre[r][0];
            if (lane < 2) Xs[ci][r][lane + 32] = pre[r][1];
        }
        __syncwarp();

        if (cg + 1 < 16) loadCG(cg + 1);

        const int c = cg*8 + ci;
        float4 wa = *(const float4*)&fws[c][0];
        float4 wb = *(const float4*)&fws[c][4];
        float w8  = fws[c][8];
        float wreg[9] = {wa.x, wa.y, wa.z, wa.w, wb.x, wb.y, wb.z, wb.w, w8};

        float f = 0.f, d = 0.f;
#pragma unroll
        for (int tap = 0; tap < 9; tap++) {
            float xv = Xs[ci][tap/3][px + (tap%3)];
            f += wreg[tap] * xv;
            d += dks[tap][px] * xv;
        }
        float dynv = fmaxf(d*s2a[c] + t2a[c], 0.f);
        float fixv = fmaxf(f*s1a[c] + t1a[c], 0.f);

        s_cat[px][c]       = __float2half_rn(dynv);
        s_cat[px][128 + c] = __float2half_rn(fixv);
        __syncwarp();
    }
    __syncthreads();

    const int opx = tid >> 3;
    const int sub = tid & 7;
    size_t base = ((size_t)(n*HW) + (size_t)h*Ww + w0 + opx)*256 + sub*32;
    const uint4* sh = (const uint4*)&s_cat[opx][sub*32];
#pragma unroll
    for (int q = 0; q < 4; q++) ((uint4*)(g_cat + base))[q] = sh[q];
}

// ---------------------------------------------------------------------------
// Weight prep: fp16 weights in K-chunked layouts
// ---------------------------------------------------------------------------
__global__ __launch_bounds__(256) void kw_prep(const float* __restrict__ jw)
{
    int idx = blockIdx.x * 256 + threadIdx.x;      // 18*128*64
    if (idx >= 18*128*64) return;
    int cidx = idx >> 13;
    int rr   = idx & 8191;
    int oc   = rr >> 6;
    int k    = rr & 63;
    int tap  = cidx >> 1;
    int ic   = (cidx & 1)*64 + k;
    g_w[idx] = __float2half_rn(jw[oc*(Cc*9) + ic*9 + tap]);
}

__global__ __launch_bounds__(256) void krw_prep(const float* __restrict__ rw)
{
    int idx = blockIdx.x * 256 + threadIdx.x;      // 4*128*64
    if (idx >= 4*128*64) return;
    int ck = idx >> 13;
    int rr = idx & 8191;
    int oc = rr >> 6;
    int k  = rr & 63;
    g_rw[idx] = __float2half_rn(rw[oc*256 + ck*64 + k]);
}

// ---------------------------------------------------------------------------
// GEMM smem: 2-stage, A at +0, W at +18432 per stage; 144B rows, one barrier
// per chunk (R12 layout).
// ---------------------------------------------------------------------------
#define STG_SZ 36864
#define SW_OFF 18432
#define GEMM_SMEM 73728

// ---------------------------------------------------------------------------
// K3: refine 1x1 as fp16 HMMA GEMM (K=256, 4 chunks).
// Epilogue: g_fused (NCHW fp32) + p=fused+coef -> g_p (NHWC fp16).
// ---------------------------------------------------------------------------
__global__ __launch_bounds__(256) void k3_mma(
    const float* __restrict__ coef,
    const float* __restrict__ rb)
{
    extern __shared__ char smem[];
    __shared__ float s_rb[128];
    const int tid = threadIdx.x;
    const int wid = tid >> 5;
    const int lane = tid & 31;
    const int p0 = blockIdx.x * 128;
    const int n  = blockIdx.z;

    if (tid < 128) s_rb[tid] = rb[tid];

    const int r  = tid >> 1;
    const int hf = tid & 1;
    const int wm = (wid & 3) * 32;
    const int wn = (wid >> 2) * 64;
    const int grp = lane >> 2;
    const int t4  = lane & 3;
    const int lr = lane & 7;
    const int lg = lane >> 3;

    const uint32_t smemU = (uint32_t)__cvta_generic_to_shared(smem);
    const uint32_t aRC = (uint32_t)(wm + (lg & 1)*8 + lr)*144 + (lg >> 1)*16;
    const uint32_t bRC = (uint32_t)(wn + (lg >> 1)*8 + lr)*144 + (lg & 1)*16;
    const uint32_t rowOff = (uint32_t)r*144 + hf*64;

    float d[2][8][4];
#pragma unroll
    for (int mf = 0; mf < 2; mf++)
#pragma unroll
        for (int nf = 0; nf < 8; nf++)
#pragma unroll
            for (int q = 0; q < 4; q++) d[mf][nf][q] = 0.f;

    uint4 va[4], vw[4];
    auto loadChunk = [&](int ck) {
        const uint4* pa = (const uint4*)(g_cat + ((size_t)(n*HW) + p0 + r)*256 + ck*64 + hf*32);
        const uint4* pw = (const uint4*)(g_rw + (size_t)ck*8192 + r*64 + hf*32);
#pragma unroll
        for (int q = 0; q < 4; q++) { va[q] = pa[q]; vw[q] = pw[q]; }
    };

    loadChunk(0);

    for (int ck = 0; ck < 4; ck++) {
        const int b = ck & 1;
        char* dst = smem + b*STG_SZ + rowOff;
#pragma unroll
        for (int q = 0; q < 4; q++) {
            *(uint4*)(dst + q*16)          = va[q];
            *(uint4*)(dst + SW_OFF + q*16) = vw[q];
        }
        __syncthreads();

        if (ck + 1 < 4) loadChunk(ck + 1);

        const uint32_t base = smemU + b*STG_SZ;
#pragma unroll
        for (int s = 0; s < 4; s++) {
            const uint32_t kb = s*32;
            uint32_t a[2][4];
#pragma unroll
            for (int mf = 0; mf < 2; mf++)
                ldmat_x4(a[mf], base + aRC + mf*(16*144) + kb);
#pragma unroll
            for (int p = 0; p < 4; p++) {
                uint32_t bw[4];
                ldmat_x4(bw, base + SW_OFF + bRC + p*(16*144) + kb);
#pragma unroll
                for (int e = 0; e < 2; e++) {
                    int nf = 2*p + e;
#pragma unroll
                    for (int mf = 0; mf < 2; mf++)
                        mma16816(d[mf][nf], a[mf], bw[2*e], bw[2*e+1]);
                }
            }
        }
    }

    __syncthreads();
    float* sD = (float*)smem;    // [128 oc][132 px]
#pragma unroll
    for (int mf = 0; mf < 2; mf++)
#pragma unroll
        for (int nf = 0; nf < 8; nf++) {
            int row = wm + mf*16 + grp;
            int col = wn + nf*8 + 2*t4;
            sD[(col  )*132 + row    ] = d[mf][nf][0];
            sD[(col+1)*132 + row    ] = d[mf][nf][1];
            sD[(col  )*132 + row + 8] = d[mf][nf][2];
            sD[(col+1)*132 + row + 8] = d[mf][nf][3];
        }
    __syncthreads();

    const size_t nplane = (size_t)n*Cc*HW;

    {
        const int pxq = (tid & 31) * 4;
#pragma unroll 2
        for (int j = 0; j < 16; j++) {
            int oc = (tid >> 5) + j*8;
            float4 a4 = *(const float4*)&sD[oc*132 + pxq];
            float b = s_rb[oc];
            float4 o = make_float4(a4.x + b, a4.y + b, a4.z + b, a4.w + b);
            *(float4*)(g_fused + nplane + (size_t)oc*HW + p0 + pxq) = o;
        }
    }

    {
        const int px2 = tid >> 1;
        const int half = tid & 1;
#pragma unroll
        for (int jj = 0; jj < 16; jj++) {
            __half hv[4];
#pragma unroll
            for (int e = 0; e < 4; e++) {
                int oc = half*64 + jj*4 + e;
                float v = sD[oc*132 + px2] + s_rb[oc]
                        + coef[nplane + (size_t)oc*HW + p0 + px2];
                hv[e] = __float2half_rn(v);
            }
            size_t dst = ((size_t)(n*HW) + p0 + px2)*128 + half*64 + jj*4;
            *(uint2*)(g_p + dst) = make_uint2(pack_h2(hv[0],hv[1]), pack_h2(hv[2],hv[3]));
        }
    }
}

// ---------------------------------------------------------------------------
// K4: joint 3x3 conv as fp16 HMMA implicit GEMM, double-buffered (1 barrier
// per chunk), register prefetch + sigmoid-gating epilogue (R12).
// ---------------------------------------------------------------------------
__global__ __launch_bounds__(256) void k4_wmma(
    const float* __restrict__ coef,
    const float* __restrict__ jb,
    float* __restrict__ out)
{
    extern __shared__ char smem[];
    const int tid = threadIdx.x;
    const int wid = tid >> 5;
    const int lane = tid & 31;
    const int w0 = blockIdx.x * 128;
    const int h  = blockIdx.y;
    const int n  = blockIdx.z;

    const int r  = tid >> 1;
    const int hf = tid & 1;
    const int wm = (wid & 3) * 32;
    const int wn = (wid >> 2) * 64;
    const int grp = lane >> 2;
    const int t4  = lane & 3;
    const int lr = lane & 7;
    const int lg = lane >> 3;

    const uint32_t smemU = (uint32_t)__cvta_generic_to_shared(smem);
    const uint32_t aRC = (uint32_t)(wm + (lg & 1)*8 + lr)*144 + (lg >> 1)*16;
    const uint32_t bRC = (uint32_t)(wn + (lg >> 1)*8 + lr)*144 + (lg & 1)*16;
    const uint32_t rowOff = (uint32_t)r*144 + hf*64;

    float d[2][8][4];
#pragma unroll
    for (int mf = 0; mf < 2; mf++)
#pragma unroll
        for (int nf = 0; nf < 8; nf++)
#pragma unroll
            for (int q = 0; q < 4; q++) d[mf][nf][q] = 0.f;

    const uint4 z4 = make_uint4(0,0,0,0);
    uint4 va[4], vw[4];

    auto loadChunk = [&](int cidx) {
        const int tap = cidx >> 1;
        const int hk  = cidx & 1;
        const int dy = tap / 3, dx = tap % 3;
        const int hh = h + dy - 1;
        const int ww = w0 + dx - 1 + r;
        const bool val = (hh >= 0 && hh < Hh && ww >= 0 && ww < Ww);
        const size_t pix = (size_t)n*HW + (size_t)hh*Ww + ww;
        const uint4* pa = (const uint4*)(g_p + pix*Cc + hk*64 + hf*32);
        const uint4* pw = (const uint4*)(g_w + (size_t)cidx*8192 + r*64 + hf*32);
#pragma unroll
        for (int q = 0; q < 4; q++) {
            va[q] = val ? pa[q] : z4;
            vw[q] = pw[q];
        }
    };

    loadChunk(0);

    for (int cidx = 0; cidx < 18; cidx++) {
        const int b = cidx & 1;
        char* dst = smem + b*STG_SZ + rowOff;
#pragma unroll
        for (int q = 0; q < 4; q++) {
            *(uint4*)(dst + q*16)          = va[q];
            *(uint4*)(dst + SW_OFF + q*16) = vw[q];
        }
        __syncthreads();

        if (cidx + 1 < 18) loadChunk(cidx + 1);

        const uint32_t base = smemU + b*STG_SZ;
#pragma unroll
        for (int s = 0; s < 4; s++) {
            const uint32_t kb = s*32;
            uint32_t a[2][4];
#pragma unroll
            for (int mf = 0; mf < 2; mf++)
                ldmat_x4(a[mf], base + aRC + mf*(16*144) + kb);
#pragma unroll
            for (int p = 0; p < 4; p++) {
                uint32_t bw[4];
                ldmat_x4(bw, base + SW_OFF + bRC + p*(16*144) + kb);
#pragma unroll
                for (int e = 0; e < 2; e++) {
                    int nf = 2*p + e;
#pragma unroll
                    for (int mf = 0; mf < 2; mf++)
                        mma16816(d[mf][nf], a[mf], bw[2*e], bw[2*e+1]);
                }
            }
        }
    }

    __syncthreads();
    float* sD = (float*)smem;
#pragma unroll
    for (int mf = 0; mf < 2; mf++)
#pragma unroll
        for (int nf = 0; nf < 8; nf++) {
            int row = wm + mf*16 + grp;
            int col = wn + nf*8 + 2*t4;
            sD[(col  )*132 + row    ] = d[mf][nf][0];
            sD[(col+1)*132 + row    ] = d[mf][nf][1];
            sD[(col  )*132 + row + 8] = d[mf][nf][2];
            sD[(col+1)*132 + row + 8] = d[mf][nf][3];
        }
    __syncthreads();

    const size_t nplane = (size_t)n*Cc*HW;
    const int px = (tid & 31) * 4;
#pragma unroll 2
    for (int j = 0; j < 16; j++) {
        int oc = (tid >> 5) + j*8;
        float4 a4 = *(const float4*)&sD[oc*132 + px];
        float b = jb[oc];
        size_t base = nplane + (size_t)oc*HW + (size_t)h*Ww + w0 + px;
        float4 fu = *(const float4*)&g_fused[base];
        float4 cf = *(const float4*)&coef[base];
        float4 o;
        { float p2 = 1.f/(1.f + __expf(-(a4.x + b))); o.x = fu.x + p2*(cf.x - fu.x); }
        { float p2 = 1.f/(1.f + __expf(-(a4.y + b))); o.y = fu.y + p2*(cf.y - fu.y); }
        { float p2 = 1.f/(1.f + __expf(-(a4.z + b))); o.z = fu.z + p2*(cf.z - fu.z); }
        { float p2 = 1.f/(1.f + __expf(-(a4.w + b))); o.w = fu.w + p2*(cf.w - fu.w); }
        *(float4*)(out + base) = o;
    }
}

// ---------------------------------------------------------------------------
extern "C" void kernel_launch(void* const* d_in, const int* in_sizes, int n_in,
                              void* d_out, int out_size)
{
    const float* coef  = (const float*)d_in[0];
    const float* ms    = (const float*)d_in[1];
    const float* fix_w = (const float*)d_in[2];
    const float* bn1_g = (const float*)d_in[3];
    const float* bn1_b = (const float*)d_in[4];
    const float* bn1_m = (const float*)d_in[5];
    const float* bn1_v = (const float*)d_in[6];
    const float* dyn_w = (const float*)d_in[7];
    const float* dyn_b = (const float*)d_in[8];
    const float* bn2_g = (const float*)d_in[9];
    const float* bn2_b = (const float*)d_in[10];
    const float* bn2_m = (const float*)d_in[11];
    const float* bn2_v = (const float*)d_in[12];
    const float* refine_w = (const float*)d_in[13];
    const float* refine_b = (const float*)d_in[14];
    const float* joint_w  = (const float*)d_in[15];
    const float* joint_b  = (const float*)d_in[16];
    float* outp = (float*)d_out;

    cudaFuncSetAttribute(k3_mma,  cudaFuncAttributeMaxDynamicSharedMemorySize, GEMM_SMEM);
    cudaFuncSetAttribute(k4_wmma, cudaFuncAttributeMaxDynamicSharedMemorySize, GEMM_SMEM);

    kw_prep<<<(18*128*64 + 255)/256, 256>>>(joint_w);
    krw_prep<<<(4*128*64 + 255)/256, 256>>>(refine_w);
    k1_dynkernel<<<dim3(Ww/128, Hh, Nn), 128>>>(ms, dyn_w, dyn_b);
    k2_cat_nhwc<<<dim3(Ww/32, Hh, Nn), 256>>>(ms, fix_w,
                                              bn1_g, bn1_b, bn1_m, bn1_v,
                                              bn2_g, bn2_b, bn2_m, bn2_v);
    k3_mma<<<dim3(HW/128, 1, Nn), 256, GEMM_SMEM>>>(coef, refine_b);
    k4_wmma<<<dim3(Ww/128, Hh, Nn), 256, GEMM_SMEM>>>(coef, joint_b, outp);
}